// round 1
// baseline (speedup 1.0000x reference)
#include <cuda_runtime.h>

// Conv(5x5, SAME, no bias) over [T=256,1,512,512] + FastLIF + FastLI scan.
// Fused: one block owns a 128x16 spatial tile, loops over all 256 timesteps,
// keeps LIF state (s1) and LI state (s2) in registers, streams x through smem.

#define TT 256
#define HH 512
#define WW 512
#define TW 128      // tile width
#define TH 16       // tile height
#define SW 136      // smem row stride (132 used cols, padded)
#define SH 20       // 16 + 4 halo rows
#define NTHREADS 256

#define ALPHA_LIF 0.85f
#define V_TH 2.0f
#define ALPHA_LI 0.9f

__global__ __launch_bounds__(NTHREADS, 1)
void snn_fused_kernel(const float* __restrict__ x,
                      const float* __restrict__ kern,
                      float* __restrict__ out)
{
    __shared__ float sm[SH][SW];

    const int tid = threadIdx.x;
    const int x0 = blockIdx.x * TW;   // 0..3  -> col offset
    const int y0 = blockIdx.y * TH;   // 0..31 -> row offset
    const int tx = tid & (TW - 1);    // 0..127 : output column within tile
    const int tq = tid >> 7;          // 0..1   : row-group
    const int yb = tq * 8;            // base output row (within tile) for this thread

    // 5x5 weights into registers (uniform across block; L1/const-cached)
    float wgt[25];
#pragma unroll
    for (int i = 0; i < 25; i++) wgt[i] = __ldg(kern + i);

    // LIF / LI state for 8 output rows
    float s1[8], s2[8];
#pragma unroll
    for (int r = 0; r < 8; r++) { s1[r] = 0.0f; s2[r] = 0.0f; }

    for (int t = 0; t < TT; t++) {
        const float* xt = x + (size_t)t * (HH * WW);

        // ---- Fill smem: rows y0-2..y0+17, cols x0-2..x0+129 (zero-padded) ----
        for (int i = tid; i < SH * 132; i += NTHREADS) {
            int rr = i / 132;
            int cc = i - rr * 132;
            int gy = y0 - 2 + rr;
            int gx = x0 - 2 + cc;
            float v = 0.0f;
            if (gy >= 0 && gy < HH && gx >= 0 && gx < WW)
                v = xt[gy * WW + gx];
            sm[rr][cc] = v;
        }
        __syncthreads();

        // ---- 5x5 conv with rolling 5x5 register window (vertical reuse) ----
        // Output row r (tile row yb+r) needs smem rows yb+r .. yb+r+4, cols tx..tx+4.
        float win[5][5];
#pragma unroll
        for (int a = 0; a < 4; a++)
#pragma unroll
            for (int b = 0; b < 5; b++)
                win[a][b] = sm[yb + a][tx + b];

        float o[8];
#pragma unroll
        for (int r = 0; r < 8; r++) {
            const int wr = (r + 4) % 5;
#pragma unroll
            for (int b = 0; b < 5; b++)
                win[wr][b] = sm[yb + r + 4][tx + b];

            float acc = 0.0f;
#pragma unroll
            for (int a = 0; a < 5; a++) {
                const int wi = (r + a) % 5;
#pragma unroll
                for (int b = 0; b < 5; b++)
                    acc = fmaf(wgt[a * 5 + b], win[wi][b], acc);
            }

            // FastLIF: leaky integrate, fire, soft reset
            float v = fmaf(ALPHA_LIF, s1[r], acc);
            float spk = (v >= V_TH) ? 1.0f : 0.0f;
            s1[r] = v - spk * V_TH;
            // FastLI readout
            s2[r] = fmaf(ALPHA_LI, s2[r], spk);
            o[r] = s2[r];
        }

        // ---- Write 8 coalesced rows ----
        float* ot = out + (size_t)t * (HH * WW) + (size_t)(y0 + yb) * WW + x0 + tx;
#pragma unroll
        for (int r = 0; r < 8; r++)
            ot[r * WW] = o[r];

        __syncthreads();  // protect smem before next timestep's fill
    }
}

extern "C" void kernel_launch(void* const* d_in, const int* in_sizes, int n_in,
                              void* d_out, int out_size)
{
    // metadata order: x [256,1,512,512] float32, kernel [1,1,5,5] float32
    const float* x = (const float*)d_in[0];
    const float* k = (const float*)d_in[1];
    if (in_sizes[0] == 25) {  // defensive: swap if metadata order differs
        const float* tmp = x; x = k; k = tmp;
    }
    float* out = (float*)d_out;

    dim3 grid(WW / TW, HH / TH);   // 4 x 32 = 128 blocks
    snn_fused_kernel<<<grid, NTHREADS>>>(x, k, out);
}

// round 2
// speedup vs baseline: 1.9670x; 1.9670x over previous
#include <cuda_runtime.h>

// Conv(5x5, SAME) over [256,1,512,512] + FastLIF + FastLI temporal scan.
// One block owns a 128x16 spatial tile for all 256 timesteps; LIF/LI state
// lives in registers. Software-pipelined: registers prefetch x[t+1] while
// computing t from double-buffered smem; one barrier per timestep.

#define TT 256
#define HH 512
#define WW 512
#define HW (HH*WW)
#define TW 128      // tile width
#define TH 16       // tile height
#define R  4        // output rows per thread
#define NT 512      // threads per block (16 warps)
#define SW 136      // smem row stride (132 used cols, padded)
#define SH 20       // 16 + 4 halo rows
#define FILLN (SH*132)            // 2640 elements per tile fill
#define PF ((FILLN + NT - 1)/NT)  // 6 prefetch slots per thread

#define ALPHA_LIF 0.85f
#define V_TH 2.0f
#define ALPHA_LI 0.9f

__global__ __launch_bounds__(NT, 1)
void snn_fused_kernel(const float* __restrict__ x,
                      const float* __restrict__ kern,
                      float* __restrict__ out)
{
    __shared__ float sm[2][SH * SW];

    const int tid = threadIdx.x;
    const int x0 = blockIdx.x * TW;
    const int y0 = blockIdx.y * TH;
    const int tx = tid & (TW - 1);     // 0..127 output column in tile
    const int yb = (tid >> 7) * R;     // base output row in tile (0,4,8,12)

    // 5x5 weights in registers (uniform, L1-cached broadcast)
    float wgt[25];
#pragma unroll
    for (int i = 0; i < 25; i++) wgt[i] = __ldg(kern + i);

    // Precompute fill-slot mapping (loop-invariant across t).
    // goff < 0 encodes "load zero" (OOB padding) or inactive slot.
    int soff[PF], goff[PF];
#pragma unroll
    for (int j = 0; j < PF; j++) {
        int i = tid + j * NT;
        if (i < FILLN) {
            int rr = i / 132, cc = i - rr * 132;
            int gy = y0 - 2 + rr, gx = x0 - 2 + cc;
            bool v = (gy >= 0 && gy < HH && gx >= 0 && gx < WW);
            soff[j] = rr * SW + cc;
            goff[j] = v ? gy * WW + gx : -1;
        } else {
            soff[j] = -1;
            goff[j] = -1;
        }
    }

    float s1[R], s2[R];
#pragma unroll
    for (int r = 0; r < R; r++) { s1[r] = 0.0f; s2[r] = 0.0f; }

    // Prefetch t=0 into registers
    float p[PF];
#pragma unroll
    for (int j = 0; j < PF; j++)
        p[j] = (goff[j] >= 0) ? __ldg(x + goff[j]) : 0.0f;

    for (int t = 0; t < TT; t++) {
        float* buf = sm[t & 1];

        // Deposit prefetched tile into this step's smem buffer
#pragma unroll
        for (int j = 0; j < PF; j++)
            if (soff[j] >= 0) buf[soff[j]] = p[j];
        __syncthreads();

        // Kick off loads for t+1 (in flight during compute below)
        if (t + 1 < TT) {
            const float* xt1 = x + (size_t)(t + 1) * HW;
#pragma unroll
            for (int j = 0; j < PF; j++)
                p[j] = (goff[j] >= 0) ? __ldg(xt1 + goff[j]) : 0.0f;
        }

        // 5x5 conv, streaming rows: each of the R+4 rows feeds up to 5 accs
        float acc[R];
#pragma unroll
        for (int r = 0; r < R; r++) acc[r] = 0.0f;

        const float* rowbase = buf + yb * SW + tx;
#pragma unroll
        for (int j = 0; j < R + 4; j++) {
            float v0 = rowbase[j * SW + 0];
            float v1 = rowbase[j * SW + 1];
            float v2 = rowbase[j * SW + 2];
            float v3 = rowbase[j * SW + 3];
            float v4 = rowbase[j * SW + 4];
#pragma unroll
            for (int r = 0; r < R; r++) {
                const int a = j - r;
                if (a >= 0 && a < 5) {
                    acc[r] = fmaf(wgt[a * 5 + 0], v0, acc[r]);
                    acc[r] = fmaf(wgt[a * 5 + 1], v1, acc[r]);
                    acc[r] = fmaf(wgt[a * 5 + 2], v2, acc[r]);
                    acc[r] = fmaf(wgt[a * 5 + 3], v3, acc[r]);
                    acc[r] = fmaf(wgt[a * 5 + 4], v4, acc[r]);
                }
            }
        }

        // LIF fire + soft reset, LI readout, coalesced store
        float* ot = out + (size_t)t * HW + (size_t)(y0 + yb) * WW + x0 + tx;
#pragma unroll
        for (int r = 0; r < R; r++) {
            float v = fmaf(ALPHA_LIF, s1[r], acc[r]);
            float spk = (v >= V_TH) ? 1.0f : 0.0f;
            s1[r] = fmaf(-spk, V_TH, v);
            s2[r] = fmaf(ALPHA_LI, s2[r], spk);
            ot[r * WW] = s2[r];
        }
        // No second barrier: next iteration's STS targets the other smem
        // buffer; the buffer read here is only overwritten two iterations
        // later, after the intervening barrier.
    }
}

extern "C" void kernel_launch(void* const* d_in, const int* in_sizes, int n_in,
                              void* d_out, int out_size)
{
    const float* x = (const float*)d_in[0];
    const float* k = (const float*)d_in[1];
    if (in_sizes[0] == 25) {  // defensive: swap if metadata order differs
        const float* tmp = x; x = k; k = tmp;
    }
    float* out = (float*)d_out;

    dim3 grid(WW / TW, HH / TH);   // 4 x 32 = 128 blocks
    snn_fused_kernel<<<grid, NT>>>(x, k, out);
}

// round 3
// speedup vs baseline: 3.9552x; 2.0108x over previous
#include <cuda_runtime.h>
#include <cstdint>

// Conv(5x5, SAME) over [256,1,512,512] + FastLIF + FastLI temporal scan.
// Tile 64x16 per block (grid 8x32 = 256 blocks), 256 threads, each thread
// computes 4 consecutive columns of one row. x streams through a triple-
// buffered smem tile filled by cp.async with zfill OOB padding, prefetched
// 2 timesteps ahead. One __syncthreads per timestep.

#define TT 256
#define HH 512
#define WW 512
#define HW (HH*WW)
#define TW 64        // tile width (outputs)
#define TH 16        // tile height (outputs)
#define NT 256       // threads per block
#define SWP 72       // smem row width: cols x0-4 .. x0+67
#define SH 20        // rows y0-2 .. y0+17
#define BUFSZ (SH*SWP + 8)       // +8 floats scratch for inactive zfill slots
#define SCRATCH (SH*SWP)
#define F4_PER_ROW 18            // 72/4
#define FILLV (SH*F4_PER_ROW)    // 360 float4 copies per tile

#define ALPHA_LIF 0.85f
#define V_TH 2.0f
#define ALPHA_LI 0.9f

__device__ __forceinline__ void cp_async16(uint32_t dst_smem, const void* src, int srcsize) {
    asm volatile("cp.async.cg.shared.global [%0], [%1], 16, %2;\n"
                 :: "r"(dst_smem), "l"(src), "r"(srcsize));
}
__device__ __forceinline__ void cp_commit() {
    asm volatile("cp.async.commit_group;\n");
}
__device__ __forceinline__ void cp_wait1() {
    asm volatile("cp.async.wait_group 1;\n");
}

__global__ __launch_bounds__(NT, 2)
void snn_fused_kernel(const float* __restrict__ x,
                      const float* __restrict__ kern,
                      float* __restrict__ out)
{
    __shared__ float sm[3][BUFSZ];

    const int tid = threadIdx.x;
    const int x0 = blockIdx.x * TW;
    const int y0 = blockIdx.y * TH;
    const int tc = tid & 15;          // thread-col group: output cols x0+4*tc..+3
    const int ty = tid >> 4;          // output row y0+ty

    // 5x5 weights in registers
    float wgt[25];
#pragma unroll
    for (int i = 0; i < 25; i++) wgt[i] = __ldg(kern + i);

    // ---- Precompute the 2 cp.async fill slots for this thread ----
    // Slot j copies float4 #(tid + j*NT) of the 20x18-float4 tile.
    // smem col 0 <-> global col x0-4 ; smem row 0 <-> global row y0-2.
    int soff[2];      // smem float offset (dst)
    int goff[2];      // global float offset (src), clamped when invalid
    int ssz[2];       // cp.async src-size: 16 = copy, 0 = zero-fill
#pragma unroll
    for (int j = 0; j < 2; j++) {
        int i = tid + j * NT;
        if (i < FILLV) {
            int rr = i / F4_PER_ROW;
            int c4 = i - rr * F4_PER_ROW;
            int gy = y0 - 2 + rr;
            int gx0 = x0 - 16 + 4 * c4;            // x0-4 in cols... (see note)
            gx0 = x0 - 4 + 4 * c4 - 0;             // global col of float4 start
            // NOTE: keep single definition:
            gx0 = x0 - 4 + 4 * c4;
            bool v = (gy >= 0) && (gy < HH) && (gx0 >= 0) && (gx0 <= WW - 4);
            soff[j] = rr * SWP + 4 * c4;
            goff[j] = v ? (gy * WW + gx0) : 0;
            ssz[j] = v ? 16 : 0;
        } else {
            soff[j] = SCRATCH;   // benign dump (zeros) for inactive slots
            goff[j] = 0;
            ssz[j] = 0;
        }
    }

    // LIF / LI state for the 4 output columns
    float s1[4] = {0.f, 0.f, 0.f, 0.f};
    float s2[4] = {0.f, 0.f, 0.f, 0.f};

    // ---- Prefetch timesteps 0 and 1 ----
#pragma unroll
    for (int t0 = 0; t0 < 2; t0++) {
        const float* xt = x + (size_t)t0 * HW;
        uint32_t base = (uint32_t)__cvta_generic_to_shared(&sm[t0][0]);
#pragma unroll
        for (int j = 0; j < 2; j++)
            cp_async16(base + 4u * soff[j], xt + goff[j], ssz[j]);
        cp_commit();
    }

    const float* rowptr0 = &sm[0][0];  // (unused; keeps types obvious)
    (void)rowptr0;

    for (int t = 0; t < TT; t++) {
        cp_wait1();          // tile for timestep t has landed (this thread's copies)
        __syncthreads();     // ... and everyone else's; also: all threads done with buf[(t+2)%3]

        // Kick off prefetch for t+2 into the buffer freed at the barrier
        {
            int t2 = t + 2;
            const float* xt = x + (size_t)t2 * HW;
            uint32_t base = (uint32_t)__cvta_generic_to_shared(&sm[t2 % 3][0]);
            if (t2 < TT) {
#pragma unroll
                for (int j = 0; j < 2; j++)
                    cp_async16(base + 4u * soff[j], xt + goff[j], ssz[j]);
            }
            cp_commit();     // unconditional: keeps wait_group accounting uniform
        }

        // ---- 5x5 conv for 4 consecutive output columns ----
        // Output col x0+4tc+c needs smem cols 4tc+2+c+b (c=0..3, b=0..4)
        // = span [4tc+2, 4tc+9]: LDS.64 + LDS.128 + LDS.64.
        const float* buf = &sm[t % 3][0];
        const float* rb = buf + ty * SWP + 4 * tc;

        float acc[4] = {0.f, 0.f, 0.f, 0.f};
#pragma unroll
        for (int a = 0; a < 5; a++) {
            const float* rp = rb + a * SWP;
            float2 u  = *(const float2*)(rp + 2);   // k0,k1
            float4 v  = *(const float4*)(rp + 4);   // k2..k5
            float2 w2 = *(const float2*)(rp + 8);   // k6,k7
            float k0 = u.x, k1 = u.y, k2 = v.x, k3 = v.y;
            float k4 = v.z, k5 = v.w, k6 = w2.x, k7 = w2.y;
            const float* wa = wgt + a * 5;
            acc[0] = fmaf(wa[0], k0, acc[0]);
            acc[0] = fmaf(wa[1], k1, acc[0]);
            acc[0] = fmaf(wa[2], k2, acc[0]);
            acc[0] = fmaf(wa[3], k3, acc[0]);
            acc[0] = fmaf(wa[4], k4, acc[0]);
            acc[1] = fmaf(wa[0], k1, acc[1]);
            acc[1] = fmaf(wa[1], k2, acc[1]);
            acc[1] = fmaf(wa[2], k3, acc[1]);
            acc[1] = fmaf(wa[3], k4, acc[1]);
            acc[1] = fmaf(wa[4], k5, acc[1]);
            acc[2] = fmaf(wa[0], k2, acc[2]);
            acc[2] = fmaf(wa[1], k3, acc[2]);
            acc[2] = fmaf(wa[2], k4, acc[2]);
            acc[2] = fmaf(wa[3], k5, acc[2]);
            acc[2] = fmaf(wa[4], k6, acc[2]);
            acc[3] = fmaf(wa[0], k3, acc[3]);
            acc[3] = fmaf(wa[1], k4, acc[3]);
            acc[3] = fmaf(wa[2], k5, acc[3]);
            acc[3] = fmaf(wa[3], k6, acc[3]);
            acc[3] = fmaf(wa[4], k7, acc[3]);
        }

        // ---- LIF fire + soft reset, LI readout ----
        float4 o;
        float* oc[4] = {&o.x, &o.y, &o.z, &o.w};
#pragma unroll
        for (int c = 0; c < 4; c++) {
            float v = fmaf(ALPHA_LIF, s1[c], acc[c]);
            float spk = (v >= V_TH) ? 1.0f : 0.0f;
            s1[c] = fmaf(spk, -V_TH, v);
            s2[c] = fmaf(ALPHA_LI, s2[c], spk);
            *oc[c] = s2[c];
        }

        // Coalesced vector store
        float* ot = out + (size_t)t * HW + (size_t)(y0 + ty) * WW + x0 + 4 * tc;
        *(float4*)ot = o;
    }
}

extern "C" void kernel_launch(void* const* d_in, const int* in_sizes, int n_in,
                              void* d_out, int out_size)
{
    const float* x = (const float*)d_in[0];
    const float* k = (const float*)d_in[1];
    if (in_sizes[0] == 25) {  // defensive: swap if metadata order differs
        const float* tmp = x; x = k; k = tmp;
    }
    float* out = (float*)d_out;

    dim3 grid(WW / TW, HH / TH);   // 8 x 32 = 256 blocks
    snn_fused_kernel<<<grid, NT>>>(x, k, out);
}